// round 8
// baseline (speedup 1.0000x reference)
#include <cuda_runtime.h>
#include <cuda_fp16.h>
#include <math.h>
#include <stdint.h>

#define BB 128
#define NN 256
#define DD 512
#define OO 512
#define MROWS (BB * NN)   // 32768

// ---------------------------------------------------------------------------
// Scratch (no cudaMalloc allowed)
// ---------------------------------------------------------------------------
__device__ __half g_x16[(size_t)MROWS * DD];   // block1: fp16(Obs); block3: fp16(h1+h2)
__device__ __half g_h1[(size_t)MROWS * OO];    // fp16 GEMM1 output
__device__ __half g_h2[(size_t)MROWS * OO];    // fp16 GEMM2 output
__device__ __half g_wg[(size_t)DD * OO];       // (g∘W)^T : [N][K] fp16
__device__ float  g_mean[MROWS];
__device__ float  g_rstd[MROWS];
__device__ float  g_S[OO];
__device__ float  g_T[OO];

// ---------------------------------------------------------------------------
// Helpers (sm_80-era PTX only — must assemble under compute_103)
// ---------------------------------------------------------------------------
__device__ __forceinline__ uint32_t smem_to_u32(const void* p) {
    uint32_t a;
    asm("{ .reg .u64 t; cvta.to.shared.u64 t, %1; cvt.u32.u64 %0, t; }"
        : "=r"(a) : "l"(p));
    return a;
}
__device__ __forceinline__ void cp16(uint32_t dst, const void* src) {
    asm volatile("cp.async.cg.shared.global [%0], [%1], 16;"
                 :: "r"(dst), "l"(src) : "memory");
}
__device__ __forceinline__ void ldm_x4(uint32_t* r, uint32_t addr) {
    asm volatile("ldmatrix.sync.aligned.m8n8.x4.shared.b16 {%0,%1,%2,%3}, [%4];"
                 : "=r"(r[0]), "=r"(r[1]), "=r"(r[2]), "=r"(r[3]) : "r"(addr));
}
__device__ __forceinline__ void mma_fp16(float* c, const uint32_t* a,
                                         uint32_t b0, uint32_t b1) {
    asm volatile(
        "mma.sync.aligned.m16n8k16.row.col.f32.f16.f16.f32 "
        "{%0,%1,%2,%3}, {%4,%5,%6,%7}, {%8,%9}, {%0,%1,%2,%3};"
        : "+f"(c[0]), "+f"(c[1]), "+f"(c[2]), "+f"(c[3])
        : "r"(a[0]), "r"(a[1]), "r"(a[2]), "r"(a[3]), "r"(b0), "r"(b1));
}

// Block-wide (128 threads) mean/rstd reduction; returns via pointers at tid==0.
__device__ __forceinline__ void row_stats_finish(float s, float ss, int row,
                                                 float* mean, float* rstd, int tid) {
    #pragma unroll
    for (int o = 16; o > 0; o >>= 1) {
        s  += __shfl_xor_sync(0xFFFFFFFFu, s,  o);
        ss += __shfl_xor_sync(0xFFFFFFFFu, ss, o);
    }
    __shared__ float sh_s[4], sh_ss[4];
    const int w = tid >> 5;
    if ((tid & 31) == 0) { sh_s[w] = s; sh_ss[w] = ss; }
    __syncthreads();
    if (tid == 0) {
        s  = sh_s[0] + sh_s[1] + sh_s[2] + sh_s[3];
        ss = sh_ss[0] + sh_ss[1] + sh_ss[2] + sh_ss[3];
        const float mn  = s * (1.0f / DD);
        const float var = ss * (1.0f / DD) - mn * mn;
        mean[row] = mn;
        rstd[row] = rsqrtf(var + 1e-5f);
    }
}

// ---------------------------------------------------------------------------
// Block 1 stats: read fp32 x, write fp16(x) + row mean/rstd (stats from fp32).
// One block per row, 128 threads.
// ---------------------------------------------------------------------------
__global__ void stats32_kernel(const float* __restrict__ x,
                               __half* __restrict__ x16,
                               float* __restrict__ mean,
                               float* __restrict__ rstd) {
    const int row = blockIdx.x;
    const int tid = threadIdx.x;
    float4 v = reinterpret_cast<const float4*>(x + (size_t)row * DD)[tid];

    __half2* p = reinterpret_cast<__half2*>(x16 + (size_t)row * DD);
    p[tid * 2]     = __halves2half2(__float2half_rn(v.x), __float2half_rn(v.y));
    p[tid * 2 + 1] = __halves2half2(__float2half_rn(v.z), __float2half_rn(v.w));

    float s  = v.x + v.y + v.z + v.w;
    float ss = v.x * v.x + v.y * v.y + v.z * v.z + v.w * v.w;
    row_stats_finish(s, ss, row, mean, rstd, tid);
}

// ---------------------------------------------------------------------------
// Stats from fp16 input (block 2: b==nullptr). For block 3 (b!=nullptr):
// forms fp16(a+b), writes it to sum_out, stats from the rounded sum.
// One block per row, 128 threads x 4 halves.
// ---------------------------------------------------------------------------
__global__ void stats16_kernel(const __half* __restrict__ a,
                               const __half* __restrict__ b,
                               __half* __restrict__ sum_out,
                               float* __restrict__ mean,
                               float* __restrict__ rstd) {
    const int row = blockIdx.x;
    const int tid = threadIdx.x;

    const float2 rawa = reinterpret_cast<const float2*>(a + (size_t)row * DD)[tid];
    __half2 a0 = *reinterpret_cast<const __half2*>(&rawa.x);
    __half2 a1 = *reinterpret_cast<const __half2*>(&rawa.y);
    float v0 = __half2float(__low2half(a0)),  v1 = __half2float(__high2half(a0));
    float v2 = __half2float(__low2half(a1)),  v3 = __half2float(__high2half(a1));

    if (b != nullptr) {
        const float2 rawb = reinterpret_cast<const float2*>(b + (size_t)row * DD)[tid];
        __half2 b0 = *reinterpret_cast<const __half2*>(&rawb.x);
        __half2 b1 = *reinterpret_cast<const __half2*>(&rawb.y);
        v0 += __half2float(__low2half(b0));  v1 += __half2float(__high2half(b0));
        v2 += __half2float(__low2half(b1));  v3 += __half2float(__high2half(b1));
        __half h0 = __float2half_rn(v0), h1 = __float2half_rn(v1);
        __half h2 = __float2half_rn(v2), h3 = __float2half_rn(v3);
        __half2* p = reinterpret_cast<__half2*>(sum_out + (size_t)row * DD);
        p[tid * 2]     = __halves2half2(h0, h1);
        p[tid * 2 + 1] = __halves2half2(h2, h3);
        // stats from the rounded values (what the GEMM will consume)
        v0 = __half2float(h0); v1 = __half2float(h1);
        v2 = __half2float(h2); v3 = __half2float(h3);
    }

    float s  = v0 + v1 + v2 + v3;
    float ss = v0 * v0 + v1 * v1 + v2 * v2 + v3 * v3;
    row_stats_finish(s, ss, row, mean, rstd, tid);
}

// ---------------------------------------------------------------------------
// Weight prep 1: wg[n*K+k] = fp16(g[k] * W[k*N+n])   (transposed, g-scaled)
// ---------------------------------------------------------------------------
__global__ void wg_kernel(const float* __restrict__ W,
                          const float* __restrict__ g,
                          __half* __restrict__ wg) {
    int idx = blockIdx.x * 256 + threadIdx.x;   // 0 .. 512*512-1
    int k = idx >> 9, n = idx & 511;
    wg[(size_t)n * DD + k] = __float2half_rn(g[k] * W[idx]);
}

// ---------------------------------------------------------------------------
// Weight prep 2: S[n] = sum_k g[k]*W[k,n],  T[n] = sum_k b[k]*W[k,n]
// grid 4 x 128 threads; thread n loops k (coalesced along n).
// ---------------------------------------------------------------------------
__global__ void st_kernel(const float* __restrict__ W,
                          const float* __restrict__ g,
                          const float* __restrict__ b,
                          float* __restrict__ S,
                          float* __restrict__ T) {
    const int n = blockIdx.x * 128 + threadIdx.x;
    float s = 0.0f, t = 0.0f;
    #pragma unroll 4
    for (int k = 0; k < DD; k++) {
        float w = W[(size_t)k * OO + n];
        s += g[k] * w;
        t += b[k] * w;
    }
    S[n] = s;
    T[n] = t;
}

// ---------------------------------------------------------------------------
// fp16 HMMA GEMM with fused LN affine epilogue:
//   out = rstd[row] * (A@Wg^T - mean[row]*S[col]) + T[col]   (+tanh)
// A raw fp16 [M,K]; Wg [N,K] fp16. CTA 128x128, BK=32, 3-stage cp.async.
// ---------------------------------------------------------------------------
template <bool TANH, typename OutT>
__global__ __launch_bounds__(256, 2)
void gemm_ln_kernel(const __half* __restrict__ A,
                    const __half* __restrict__ B,
                    const float* __restrict__ mean,
                    const float* __restrict__ rstd,
                    const float* __restrict__ S,
                    const float* __restrict__ T,
                    OutT* __restrict__ C) {
    extern __shared__ char smem[];
    const uint32_t sb = smem_to_u32(smem);

    const int tid  = threadIdx.x;
    const int lane = tid & 31;
    const int wid  = tid >> 5;
    const int m0 = blockIdx.y * 128;
    const int n0 = blockIdx.x * 128;
    const int warp_m = (wid >> 1) * 32;
    const int warp_n = (wid & 1) * 64;

    float acc[2][8][4];
    #pragma unroll
    for (int i = 0; i < 2; i++)
        #pragma unroll
        for (int j = 0; j < 8; j++)
            #pragma unroll
            for (int q = 0; q < 4; q++) acc[i][j][q] = 0.0f;

    const int arow  = warp_m + (lane & 7) + ((lane >> 3) & 1) * 8;
    const int akblk = (lane >> 4) & 1;
    const int ax    = arow & 3;
    const int brow  = warp_n + (lane & 7) + ((lane >> 4) & 1) * 8;
    const int bkblk = (lane >> 3) & 1;
    const int bx    = brow & 3;

    #define AOFF(mt, kb) \
        (uint32_t)((arow + (mt) * 16) * 64 + (((((kb) >> 3) + akblk) ^ ax) & 3) * 16)
    #define BOFF(jj, kb) \
        (uint32_t)((brow + (jj) * 16) * 64 + (((((kb) >> 3) + bkblk) ^ bx) & 3) * 16)

    const int c0row = tid >> 2,          c0ch = tid & 3;
    const int c1row = (tid + 256) >> 2;
    const uint32_t d0 = (uint32_t)(c0row * 64 + ((c0ch ^ (c0row & 3)) << 4));
    const uint32_t d1 = (uint32_t)(c1row * 64 + ((c0ch ^ (c1row & 3)) << 4));
    const size_t gA0 = (size_t)(m0 + c0row) * DD + c0ch * 8;
    const size_t gA1 = (size_t)(m0 + c1row) * DD + c0ch * 8;
    const size_t gB0 = (size_t)(n0 + c0row) * DD + c0ch * 8;
    const size_t gB1 = (size_t)(n0 + c1row) * DD + c0ch * 8;

    #define LOAD_STAGE(it, st) do {                                      \
        const int _k0 = (it) * 32;                                       \
        const uint32_t _sa = sb + (uint32_t)(st) * 16384u;               \
        const uint32_t _sbb = _sa + 8192u;                               \
        cp16(_sa + d0, A + gA0 + _k0);                                   \
        cp16(_sa + d1, A + gA1 + _k0);                                   \
        cp16(_sbb + d0, B + gB0 + _k0);                                  \
        cp16(_sbb + d1, B + gB1 + _k0);                                  \
        asm volatile("cp.async.commit_group;" ::: "memory");             \
    } while (0)

    LOAD_STAGE(0, 0);
    LOAD_STAGE(1, 1);

    const int NK = DD / 32;   // 16
    int st = 0;
    for (int it = 0; it < NK; it++) {
        if (it + 1 < NK) {
            asm volatile("cp.async.wait_group 1;" ::: "memory");
        } else {
            asm volatile("cp.async.wait_group 0;" ::: "memory");
        }
        __syncthreads();

        if (it + 2 < NK) {
            int st2 = st + 2; if (st2 >= 3) st2 -= 3;
            LOAD_STAGE(it + 2, st2);
        }

        const uint32_t sa = sb + (uint32_t)st * 16384u;
        const uint32_t sbB = sa + 8192u;
        #pragma unroll
        for (int ks = 0; ks < 2; ks++) {
            const int kb = ks * 16;
            uint32_t af[2][4];
            #pragma unroll
            for (int mt = 0; mt < 2; mt++)
                ldm_x4(af[mt], sa + AOFF(mt, kb));
            uint32_t bf[4][4];
            #pragma unroll
            for (int jj = 0; jj < 4; jj++)
                ldm_x4(bf[jj], sbB + BOFF(jj, kb));
            #pragma unroll
            for (int j = 0; j < 8; j++) {
                const int jj = j >> 1, jh = (j & 1) * 2;
                const uint32_t b0 = bf[jj][jh], b1 = bf[jj][jh + 1];
                #pragma unroll
                for (int mt = 0; mt < 2; mt++)
                    mma_fp16(acc[mt][j], af[mt], b0, b1);
            }
        }
        if (++st >= 3) st = 0;
    }
    #undef LOAD_STAGE
    #undef AOFF
    #undef BOFF

    // Epilogue: fused LN affine (+tanh), write OutT
    #pragma unroll
    for (int mt = 0; mt < 2; mt++) {
        const int r0 = m0 + warp_m + mt * 16 + (lane >> 2);
        const int r1 = r0 + 8;
        const float mn0 = mean[r0], rs0 = rstd[r0];
        const float mn1 = mean[r1], rs1 = rstd[r1];
        #pragma unroll
        for (int j = 0; j < 8; j++) {
            const int col = n0 + warp_n + j * 8 + (lane & 3) * 2;
            const float s0 = S[col], s1 = S[col + 1];
            const float t0 = T[col], t1 = T[col + 1];
            float v0 = rs0 * (acc[mt][j][0] - mn0 * s0) + t0;
            float v1 = rs0 * (acc[mt][j][1] - mn0 * s1) + t1;
            float v2 = rs1 * (acc[mt][j][2] - mn1 * s0) + t0;
            float v3 = rs1 * (acc[mt][j][3] - mn1 * s1) + t1;
            if (TANH) { v0 = tanhf(v0); v1 = tanhf(v1); v2 = tanhf(v2); v3 = tanhf(v3); }
            if (sizeof(OutT) == 2) {
                __half2* p0 = reinterpret_cast<__half2*>((__half*)C + (size_t)r0 * OO + col);
                __half2* p1 = reinterpret_cast<__half2*>((__half*)C + (size_t)r1 * OO + col);
                *p0 = __halves2half2(__float2half_rn(v0), __float2half_rn(v1));
                *p1 = __halves2half2(__float2half_rn(v2), __float2half_rn(v3));
            } else {
                *reinterpret_cast<float2*>((float*)C + (size_t)r0 * OO + col) = make_float2(v0, v1);
                *reinterpret_cast<float2*>((float*)C + (size_t)r1 * OO + col) = make_float2(v2, v3);
            }
        }
    }
}

// ---------------------------------------------------------------------------
// Masked softmax over axis=1 (N=256), in-place on out[B, N, O].
// grid (BB, 4): each block handles 128 output channels with 128 threads.
// ---------------------------------------------------------------------------
__global__ __launch_bounds__(128)
void softmax_kernel(float* __restrict__ out, const unsigned* __restrict__ mask) {
    const int b = blockIdx.x;
    const int o = blockIdx.y * 128 + threadIdx.x;

    __shared__ unsigned smask[NN];
    smask[threadIdx.x]       = mask[(size_t)b * NN + threadIdx.x];
    smask[threadIdx.x + 128] = mask[(size_t)b * NN + threadIdx.x + 128];
    __syncthreads();

    int my = (smask[threadIdx.x] != 0u) | (smask[threadIdx.x + 128] != 0u);
    int any = __syncthreads_or(my);
    if (!any && threadIdx.x == 0) smask[0] = 1u;
    __syncthreads();

    float* base = out + (size_t)b * NN * OO + o;

    float m = -INFINITY, s = 0.0f;
    for (int n = 0; n < NN; n++) {
        if (smask[n]) {
            float v = base[(size_t)n * OO];
            float nm = fmaxf(m, v);
            s = s * __expf(m - nm) + __expf(v - nm);
            m = nm;
        }
    }

    const float rs = 1.0f / s;
    for (int n = 0; n < NN; n++) {
        float v = smask[n] ? __expf(base[(size_t)n * OO] - m) * rs : 0.0f;
        base[(size_t)n * OO] = v;
    }
}

// ---------------------------------------------------------------------------
// Launch
// ---------------------------------------------------------------------------
extern "C" void kernel_launch(void* const* d_in, const int* in_sizes, int n_in,
                              void* d_out, int out_size) {
    const float*    Obs  = (const float*)d_in[0];
    const unsigned* mask = (const unsigned*)d_in[1];
    const float* g1 = (const float*)d_in[2];
    const float* b1 = (const float*)d_in[3];
    const float* W1 = (const float*)d_in[4];
    const float* g2 = (const float*)d_in[5];
    const float* b2 = (const float*)d_in[6];
    const float* W2 = (const float*)d_in[7];
    const float* g3 = (const float*)d_in[8];
    const float* b3 = (const float*)d_in[9];
    const float* W3 = (const float*)d_in[10];
    float* out = (float*)d_out;

    __half *x16, *h1, *h2, *wg;
    float *mean, *rstd, *S, *T;
    cudaGetSymbolAddress((void**)&x16, g_x16);
    cudaGetSymbolAddress((void**)&h1, g_h1);
    cudaGetSymbolAddress((void**)&h2, g_h2);
    cudaGetSymbolAddress((void**)&wg, g_wg);
    cudaGetSymbolAddress((void**)&mean, g_mean);
    cudaGetSymbolAddress((void**)&rstd, g_rstd);
    cudaGetSymbolAddress((void**)&S, g_S);
    cudaGetSymbolAddress((void**)&T, g_T);

    static bool attr_done = false;
    const int DSMEM = 49152;   // 3 stages x 16KB
    if (!attr_done) {
        cudaFuncSetAttribute(gemm_ln_kernel<true, __half>,
                             cudaFuncAttributeMaxDynamicSharedMemorySize, DSMEM);
        cudaFuncSetAttribute(gemm_ln_kernel<false, float>,
                             cudaFuncAttributeMaxDynamicSharedMemorySize, DSMEM);
        attr_done = true;
    }

    const dim3 gGemm(OO / 128, MROWS / 128);

    // Block 1: stats(Obs) + fp16 convert; Wg1/S1/T1; GEMM -> h1 (fp16)
    stats32_kernel<<<MROWS, 128>>>(Obs, x16, mean, rstd);
    wg_kernel<<<(DD * OO) / 256, 256>>>(W1, g1, wg);
    st_kernel<<<4, 128>>>(W1, g1, b1, S, T);
    gemm_ln_kernel<true, __half><<<gGemm, 256, DSMEM>>>(x16, wg, mean, rstd, S, T, h1);

    // Block 2: stats(h1); Wg2/S2/T2; GEMM -> h2 (fp16)
    stats16_kernel<<<MROWS, 128>>>(h1, nullptr, nullptr, mean, rstd);
    wg_kernel<<<(DD * OO) / 256, 256>>>(W2, g2, wg);
    st_kernel<<<4, 128>>>(W2, g2, b2, S, T);
    gemm_ln_kernel<true, __half><<<gGemm, 256, DSMEM>>>(h1, wg, mean, rstd, S, T, h2);

    // Block 3: stats(h1+h2) + fp16 sum; Wg3/S3/T3; GEMM -> out (fp32)
    stats16_kernel<<<MROWS, 128>>>(h1, h2, x16, mean, rstd);
    wg_kernel<<<(DD * OO) / 256, 256>>>(W3, g3, wg);
    st_kernel<<<4, 128>>>(W3, g3, b3, S, T);
    gemm_ln_kernel<false, float><<<gGemm, 256, DSMEM>>>(x16, wg, mean, rstd, S, T, out);

    // Masked softmax over axis=1, in place
    softmax_kernel<<<dim3(BB, 4), 128>>>(out, mask);
}

// round 9
// speedup vs baseline: 1.2276x; 1.2276x over previous
#include <cuda_runtime.h>
#include <cuda_fp16.h>
#include <math.h>
#include <stdint.h>

#define BB 128
#define NN 256
#define DD 512
#define OO 512
#define MROWS (BB * NN)   // 32768

// ---------------------------------------------------------------------------
// Scratch (no cudaMalloc allowed)
// ---------------------------------------------------------------------------
__device__ __half g_x16[(size_t)MROWS * DD];   // block1: fp16(Obs); block3: fp16(h1+h2)
__device__ __half g_h1[(size_t)MROWS * OO];    // fp16 GEMM1 output
__device__ __half g_h2[(size_t)MROWS * OO];    // fp16 GEMM2 output
__device__ __half g_wg[(size_t)DD * OO];       // (g∘W)^T : [N][K] fp16
__device__ float  g_mean[MROWS];
__device__ float  g_rstd[MROWS];
__device__ float  g_S[OO];
__device__ float  g_T[OO];
__device__ float  g_Sp[64 * OO];
__device__ float  g_Tp[64 * OO];

// ---------------------------------------------------------------------------
// Helpers (sm_80-era PTX only — must assemble under compute_103)
// ---------------------------------------------------------------------------
__device__ __forceinline__ uint32_t smem_to_u32(const void* p) {
    uint32_t a;
    asm("{ .reg .u64 t; cvta.to.shared.u64 t, %1; cvt.u32.u64 %0, t; }"
        : "=r"(a) : "l"(p));
    return a;
}
__device__ __forceinline__ void cp16(uint32_t dst, const void* src) {
    asm volatile("cp.async.cg.shared.global [%0], [%1], 16;"
                 :: "r"(dst), "l"(src) : "memory");
}
__device__ __forceinline__ void ldm_x4(uint32_t* r, uint32_t addr) {
    asm volatile("ldmatrix.sync.aligned.m8n8.x4.shared.b16 {%0,%1,%2,%3}, [%4];"
                 : "=r"(r[0]), "=r"(r[1]), "=r"(r[2]), "=r"(r[3]) : "r"(addr));
}
__device__ __forceinline__ void mma_fp16(float* c, const uint32_t* a,
                                         uint32_t b0, uint32_t b1) {
    asm volatile(
        "mma.sync.aligned.m16n8k16.row.col.f32.f16.f16.f32 "
        "{%0,%1,%2,%3}, {%4,%5,%6,%7}, {%8,%9}, {%0,%1,%2,%3};"
        : "+f"(c[0]), "+f"(c[1]), "+f"(c[2]), "+f"(c[3])
        : "r"(a[0]), "r"(a[1]), "r"(a[2]), "r"(a[3]), "r"(b0), "r"(b1));
}

// Block-wide (128 threads) mean/rstd reduction.
__device__ __forceinline__ void row_stats_finish(float s, float ss, int row,
                                                 float* mean, float* rstd, int tid) {
    #pragma unroll
    for (int o = 16; o > 0; o >>= 1) {
        s  += __shfl_xor_sync(0xFFFFFFFFu, s,  o);
        ss += __shfl_xor_sync(0xFFFFFFFFu, ss, o);
    }
    __shared__ float sh_s[4], sh_ss[4];
    const int w = tid >> 5;
    if ((tid & 31) == 0) { sh_s[w] = s; sh_ss[w] = ss; }
    __syncthreads();
    if (tid == 0) {
        s  = sh_s[0] + sh_s[1] + sh_s[2] + sh_s[3];
        ss = sh_ss[0] + sh_ss[1] + sh_ss[2] + sh_ss[3];
        const float mn  = s * (1.0f / DD);
        const float var = ss * (1.0f / DD) - mn * mn;
        mean[row] = mn;
        rstd[row] = rsqrtf(var + 1e-5f);
    }
}

// ---------------------------------------------------------------------------
// Block 1 stats: read fp32 x, write fp16(x) + row mean/rstd (stats from fp32).
// ---------------------------------------------------------------------------
__global__ void stats32_kernel(const float* __restrict__ x,
                               __half* __restrict__ x16,
                               float* __restrict__ mean,
                               float* __restrict__ rstd) {
    const int row = blockIdx.x;
    const int tid = threadIdx.x;
    float4 v = reinterpret_cast<const float4*>(x + (size_t)row * DD)[tid];

    __half2* p = reinterpret_cast<__half2*>(x16 + (size_t)row * DD);
    p[tid * 2]     = __halves2half2(__float2half_rn(v.x), __float2half_rn(v.y));
    p[tid * 2 + 1] = __halves2half2(__float2half_rn(v.z), __float2half_rn(v.w));

    float s  = v.x + v.y + v.z + v.w;
    float ss = v.x * v.x + v.y * v.y + v.z * v.z + v.w * v.w;
    row_stats_finish(s, ss, row, mean, rstd, tid);
}

// ---------------------------------------------------------------------------
// Stats from fp16 input (block 2: b==nullptr). Block 3 (b!=nullptr):
// forms fp16(a+b), writes to sum_out, stats from the rounded sum.
// ---------------------------------------------------------------------------
__global__ void stats16_kernel(const __half* __restrict__ a,
                               const __half* __restrict__ b,
                               __half* __restrict__ sum_out,
                               float* __restrict__ mean,
                               float* __restrict__ rstd) {
    const int row = blockIdx.x;
    const int tid = threadIdx.x;

    const float2 rawa = reinterpret_cast<const float2*>(a + (size_t)row * DD)[tid];
    __half2 a0 = *reinterpret_cast<const __half2*>(&rawa.x);
    __half2 a1 = *reinterpret_cast<const __half2*>(&rawa.y);
    float v0 = __half2float(__low2half(a0)),  v1 = __half2float(__high2half(a0));
    float v2 = __half2float(__low2half(a1)),  v3 = __half2float(__high2half(a1));

    if (b != nullptr) {
        const float2 rawb = reinterpret_cast<const float2*>(b + (size_t)row * DD)[tid];
        __half2 b0 = *reinterpret_cast<const __half2*>(&rawb.x);
        __half2 b1 = *reinterpret_cast<const __half2*>(&rawb.y);
        v0 += __half2float(__low2half(b0));  v1 += __half2float(__high2half(b0));
        v2 += __half2float(__low2half(b1));  v3 += __half2float(__high2half(b1));
        __half h0 = __float2half_rn(v0), h1 = __float2half_rn(v1);
        __half h2 = __float2half_rn(v2), h3 = __float2half_rn(v3);
        __half2* p = reinterpret_cast<__half2*>(sum_out + (size_t)row * DD);
        p[tid * 2]     = __halves2half2(h0, h1);
        p[tid * 2 + 1] = __halves2half2(h2, h3);
        v0 = __half2float(h0); v1 = __half2float(h1);
        v2 = __half2float(h2); v3 = __half2float(h3);
    }

    float s  = v0 + v1 + v2 + v3;
    float ss = v0 * v0 + v1 * v1 + v2 * v2 + v3 * v3;
    row_stats_finish(s, ss, row, mean, rstd, tid);
}

// ---------------------------------------------------------------------------
// Weight prep 1: wg[n*K+k] = fp16(g[k] * W[k*N+n])   (transposed, g-scaled)
// ---------------------------------------------------------------------------
__global__ void wg_kernel(const float* __restrict__ W,
                          const float* __restrict__ g,
                          __half* __restrict__ wg) {
    int idx = blockIdx.x * 256 + threadIdx.x;
    int k = idx >> 9, n = idx & 511;
    wg[(size_t)n * DD + k] = __float2half_rn(g[k] * W[idx]);
}

// ---------------------------------------------------------------------------
// S/T phase 1: 64 blocks x 256 threads. Block i reduces k in [8i, 8i+8) for
// all 512 columns (coalesced). Thread handles columns tid and tid+256.
// ---------------------------------------------------------------------------
__global__ void stp_kernel(const float* __restrict__ W,
                           const float* __restrict__ g,
                           const float* __restrict__ b,
                           float* __restrict__ Sp,
                           float* __restrict__ Tp) {
    const int k0 = blockIdx.x * 8;
    const int n0 = threadIdx.x;
    const int n1 = threadIdx.x + 256;
    float s0 = 0.f, t0 = 0.f, s1 = 0.f, t1 = 0.f;
    #pragma unroll
    for (int i = 0; i < 8; i++) {
        const int k = k0 + i;
        const float gk = g[k], bk = b[k];
        const float w0 = W[(size_t)k * OO + n0];
        const float w1 = W[(size_t)k * OO + n1];
        s0 += gk * w0; t0 += bk * w0;
        s1 += gk * w1; t1 += bk * w1;
    }
    Sp[blockIdx.x * OO + n0] = s0;  Tp[blockIdx.x * OO + n0] = t0;
    Sp[blockIdx.x * OO + n1] = s1;  Tp[blockIdx.x * OO + n1] = t1;
}

// ---------------------------------------------------------------------------
// S/T phase 2: 2 blocks x 256 threads; column n sums 64 partials (coalesced).
// ---------------------------------------------------------------------------
__global__ void str_kernel(const float* __restrict__ Sp,
                           const float* __restrict__ Tp,
                           float* __restrict__ S,
                           float* __restrict__ T) {
    const int n = blockIdx.x * 256 + threadIdx.x;
    float s = 0.f, t = 0.f;
    #pragma unroll 8
    for (int i = 0; i < 64; i++) {
        s += Sp[i * OO + n];
        t += Tp[i * OO + n];
    }
    S[n] = s;
    T[n] = t;
}

// ---------------------------------------------------------------------------
// fp16 HMMA GEMM with fused LN affine epilogue:
//   out = rstd[row] * (A@Wg^T - mean[row]*S[col]) + T[col]   (+tanh)
// A raw fp16 [M,K]; Wg [N,K] fp16. CTA 128x128, BK=32, 3-stage cp.async.
// ---------------------------------------------------------------------------
template <bool TANH, typename OutT>
__global__ __launch_bounds__(256, 2)
void gemm_ln_kernel(const __half* __restrict__ A,
                    const __half* __restrict__ B,
                    const float* __restrict__ mean,
                    const float* __restrict__ rstd,
                    const float* __restrict__ S,
                    const float* __restrict__ T,
                    OutT* __restrict__ C) {
    extern __shared__ char smem[];
    const uint32_t sb = smem_to_u32(smem);

    const int tid  = threadIdx.x;
    const int lane = tid & 31;
    const int wid  = tid >> 5;
    const int m0 = blockIdx.y * 128;
    const int n0 = blockIdx.x * 128;
    const int warp_m = (wid >> 1) * 32;
    const int warp_n = (wid & 1) * 64;

    float acc[2][8][4];
    #pragma unroll
    for (int i = 0; i < 2; i++)
        #pragma unroll
        for (int j = 0; j < 8; j++)
            #pragma unroll
            for (int q = 0; q < 4; q++) acc[i][j][q] = 0.0f;

    const int arow  = warp_m + (lane & 7) + ((lane >> 3) & 1) * 8;
    const int akblk = (lane >> 4) & 1;
    const int ax    = arow & 3;
    const int brow  = warp_n + (lane & 7) + ((lane >> 4) & 1) * 8;
    const int bkblk = (lane >> 3) & 1;
    const int bx    = brow & 3;

    #define AOFF(mt, kb) \
        (uint32_t)((arow + (mt) * 16) * 64 + (((((kb) >> 3) + akblk) ^ ax) & 3) * 16)
    #define BOFF(jj, kb) \
        (uint32_t)((brow + (jj) * 16) * 64 + (((((kb) >> 3) + bkblk) ^ bx) & 3) * 16)

    const int c0row = tid >> 2,          c0ch = tid & 3;
    const int c1row = (tid + 256) >> 2;
    const uint32_t d0 = (uint32_t)(c0row * 64 + ((c0ch ^ (c0row & 3)) << 4));
    const uint32_t d1 = (uint32_t)(c1row * 64 + ((c0ch ^ (c1row & 3)) << 4));
    const size_t gA0 = (size_t)(m0 + c0row) * DD + c0ch * 8;
    const size_t gA1 = (size_t)(m0 + c1row) * DD + c0ch * 8;
    const size_t gB0 = (size_t)(n0 + c0row) * DD + c0ch * 8;
    const size_t gB1 = (size_t)(n0 + c1row) * DD + c0ch * 8;

    #define LOAD_STAGE(it, st) do {                                      \
        const int _k0 = (it) * 32;                                       \
        const uint32_t _sa = sb + (uint32_t)(st) * 16384u;               \
        const uint32_t _sbb = _sa + 8192u;                               \
        cp16(_sa + d0, A + gA0 + _k0);                                   \
        cp16(_sa + d1, A + gA1 + _k0);                                   \
        cp16(_sbb + d0, B + gB0 + _k0);                                  \
        cp16(_sbb + d1, B + gB1 + _k0);                                  \
        asm volatile("cp.async.commit_group;" ::: "memory");             \
    } while (0)

    LOAD_STAGE(0, 0);
    LOAD_STAGE(1, 1);

    const int NK = DD / 32;   // 16
    int st = 0;
    for (int it = 0; it < NK; it++) {
        if (it + 1 < NK) {
            asm volatile("cp.async.wait_group 1;" ::: "memory");
        } else {
            asm volatile("cp.async.wait_group 0;" ::: "memory");
        }
        __syncthreads();

        if (it + 2 < NK) {
            int st2 = st + 2; if (st2 >= 3) st2 -= 3;
            LOAD_STAGE(it + 2, st2);
        }

        const uint32_t sa = sb + (uint32_t)st * 16384u;
        const uint32_t sbB = sa + 8192u;
        #pragma unroll
        for (int ks = 0; ks < 2; ks++) {
            const int kb = ks * 16;
            uint32_t af[2][4];
            #pragma unroll
            for (int mt = 0; mt < 2; mt++)
                ldm_x4(af[mt], sa + AOFF(mt, kb));
            uint32_t bf[4][4];
            #pragma unroll
            for (int jj = 0; jj < 4; jj++)
                ldm_x4(bf[jj], sbB + BOFF(jj, kb));
            #pragma unroll
            for (int j = 0; j < 8; j++) {
                const int jj = j >> 1, jh = (j & 1) * 2;
                const uint32_t b0 = bf[jj][jh], b1 = bf[jj][jh + 1];
                #pragma unroll
                for (int mt = 0; mt < 2; mt++)
                    mma_fp16(acc[mt][j], af[mt], b0, b1);
            }
        }
        if (++st >= 3) st = 0;
    }
    #undef LOAD_STAGE
    #undef AOFF
    #undef BOFF

    // Epilogue: fused LN affine (+tanh), write OutT
    #pragma unroll
    for (int mt = 0; mt < 2; mt++) {
        const int r0 = m0 + warp_m + mt * 16 + (lane >> 2);
        const int r1 = r0 + 8;
        const float mn0 = mean[r0], rs0 = rstd[r0];
        const float mn1 = mean[r1], rs1 = rstd[r1];
        #pragma unroll
        for (int j = 0; j < 8; j++) {
            const int col = n0 + warp_n + j * 8 + (lane & 3) * 2;
            const float s0 = S[col], s1 = S[col + 1];
            const float t0 = T[col], t1 = T[col + 1];
            float v0 = rs0 * (acc[mt][j][0] - mn0 * s0) + t0;
            float v1 = rs0 * (acc[mt][j][1] - mn0 * s1) + t1;
            float v2 = rs1 * (acc[mt][j][2] - mn1 * s0) + t0;
            float v3 = rs1 * (acc[mt][j][3] - mn1 * s1) + t1;
            if (TANH) { v0 = tanhf(v0); v1 = tanhf(v1); v2 = tanhf(v2); v3 = tanhf(v3); }
            if (sizeof(OutT) == 2) {
                __half2* p0 = reinterpret_cast<__half2*>((__half*)C + (size_t)r0 * OO + col);
                __half2* p1 = reinterpret_cast<__half2*>((__half*)C + (size_t)r1 * OO + col);
                *p0 = __halves2half2(__float2half_rn(v0), __float2half_rn(v1));
                *p1 = __halves2half2(__float2half_rn(v2), __float2half_rn(v3));
            } else {
                *reinterpret_cast<float2*>((float*)C + (size_t)r0 * OO + col) = make_float2(v0, v1);
                *reinterpret_cast<float2*>((float*)C + (size_t)r1 * OO + col) = make_float2(v2, v3);
            }
        }
    }
}

// ---------------------------------------------------------------------------
// Masked softmax over axis=1 (N=256), in-place on out[B, N, O].
// grid (BB, 4): each block handles 128 output channels with 128 threads.
// ---------------------------------------------------------------------------
__global__ __launch_bounds__(128)
void softmax_kernel(float* __restrict__ out, const unsigned* __restrict__ mask) {
    const int b = blockIdx.x;
    const int o = blockIdx.y * 128 + threadIdx.x;

    __shared__ unsigned smask[NN];
    smask[threadIdx.x]       = mask[(size_t)b * NN + threadIdx.x];
    smask[threadIdx.x + 128] = mask[(size_t)b * NN + threadIdx.x + 128];
    __syncthreads();

    int my = (smask[threadIdx.x] != 0u) | (smask[threadIdx.x + 128] != 0u);
    int any = __syncthreads_or(my);
    if (!any && threadIdx.x == 0) smask[0] = 1u;
    __syncthreads();

    float* base = out + (size_t)b * NN * OO + o;

    float m = -INFINITY, s = 0.0f;
    for (int n = 0; n < NN; n++) {
        if (smask[n]) {
            float v = base[(size_t)n * OO];
            float nm = fmaxf(m, v);
            s = s * __expf(m - nm) + __expf(v - nm);
            m = nm;
        }
    }

    const float rs = 1.0f / s;
    for (int n = 0; n < NN; n++) {
        float v = smask[n] ? __expf(base[(size_t)n * OO] - m) * rs : 0.0f;
        base[(size_t)n * OO] = v;
    }
}

// ---------------------------------------------------------------------------
// Launch
// ---------------------------------------------------------------------------
extern "C" void kernel_launch(void* const* d_in, const int* in_sizes, int n_in,
                              void* d_out, int out_size) {
    const float*    Obs  = (const float*)d_in[0];
    const unsigned* mask = (const unsigned*)d_in[1];
    const float* g1 = (const float*)d_in[2];
    const float* b1 = (const float*)d_in[3];
    const float* W1 = (const float*)d_in[4];
    const float* g2 = (const float*)d_in[5];
    const float* b2 = (const float*)d_in[6];
    const float* W2 = (const float*)d_in[7];
    const float* g3 = (const float*)d_in[8];
    const float* b3 = (const float*)d_in[9];
    const float* W3 = (const float*)d_in[10];
    float* out = (float*)d_out;

    __half *x16, *h1, *h2, *wg;
    float *mean, *rstd, *S, *T, *Sp, *Tp;
    cudaGetSymbolAddress((void**)&x16, g_x16);
    cudaGetSymbolAddress((void**)&h1, g_h1);
    cudaGetSymbolAddress((void**)&h2, g_h2);
    cudaGetSymbolAddress((void**)&wg, g_wg);
    cudaGetSymbolAddress((void**)&mean, g_mean);
    cudaGetSymbolAddress((void**)&rstd, g_rstd);
    cudaGetSymbolAddress((void**)&S, g_S);
    cudaGetSymbolAddress((void**)&T, g_T);
    cudaGetSymbolAddress((void**)&Sp, g_Sp);
    cudaGetSymbolAddress((void**)&Tp, g_Tp);

    static bool attr_done = false;
    const int DSMEM = 49152;   // 3 stages x 16KB
    if (!attr_done) {
        cudaFuncSetAttribute(gemm_ln_kernel<true, __half>,
                             cudaFuncAttributeMaxDynamicSharedMemorySize, DSMEM);
        cudaFuncSetAttribute(gemm_ln_kernel<false, float>,
                             cudaFuncAttributeMaxDynamicSharedMemorySize, DSMEM);
        attr_done = true;
    }

    const dim3 gGemm(OO / 128, MROWS / 128);

    // Block 1: stats(Obs) + fp16 convert; Wg1/S1/T1; GEMM -> h1 (fp16)
    stats32_kernel<<<MROWS, 128>>>(Obs, x16, mean, rstd);
    wg_kernel<<<(DD * OO) / 256, 256>>>(W1, g1, wg);
    stp_kernel<<<64, 256>>>(W1, g1, b1, Sp, Tp);
    str_kernel<<<2, 256>>>(Sp, Tp, S, T);
    gemm_ln_kernel<true, __half><<<gGemm, 256, DSMEM>>>(x16, wg, mean, rstd, S, T, h1);

    // Block 2: stats(h1); Wg2/S2/T2; GEMM -> h2 (fp16)
    stats16_kernel<<<MROWS, 128>>>(h1, nullptr, nullptr, mean, rstd);
    wg_kernel<<<(DD * OO) / 256, 256>>>(W2, g2, wg);
    stp_kernel<<<64, 256>>>(W2, g2, b2, Sp, Tp);
    str_kernel<<<2, 256>>>(Sp, Tp, S, T);
    gemm_ln_kernel<true, __half><<<gGemm, 256, DSMEM>>>(h1, wg, mean, rstd, S, T, h2);

    // Block 3: stats(h1+h2) + fp16 sum; Wg3/S3/T3; GEMM -> out (fp32)
    stats16_kernel<<<MROWS, 128>>>(h1, h2, x16, mean, rstd);
    wg_kernel<<<(DD * OO) / 256, 256>>>(W3, g3, wg);
    stp_kernel<<<64, 256>>>(W3, g3, b3, Sp, Tp);
    str_kernel<<<2, 256>>>(Sp, Tp, S, T);
    gemm_ln_kernel<false, float><<<gGemm, 256, DSMEM>>>(x16, wg, mean, rstd, S, T, out);

    // Masked softmax over axis=1, in place
    softmax_kernel<<<dim3(BB, 4), 128>>>(out, mask);
}

// round 10
// speedup vs baseline: 1.3771x; 1.1217x over previous
#include <cuda_runtime.h>
#include <cuda_fp16.h>
#include <math.h>
#include <stdint.h>

#define BB 128
#define NN 256
#define DD 512
#define OO 512
#define MROWS (BB * NN)   // 32768

// ---------------------------------------------------------------------------
// Scratch (no cudaMalloc allowed)
// ---------------------------------------------------------------------------
__device__ __half g_x16[(size_t)MROWS * DD];       // block1: fp16(Obs); block3: fp16(h1+h2)
__device__ __half g_h1[(size_t)MROWS * OO];        // fp16 GEMM1 output
__device__ __half g_h2[(size_t)MROWS * OO];        // fp16 GEMM2 output
__device__ __half g_wg[3 * (size_t)DD * OO];       // (g∘W)^T per layer: [N][K] fp16
__device__ float  g_mean[MROWS];
__device__ float  g_rstd[MROWS];
__device__ float  g_S[3 * OO];
__device__ float  g_T[3 * OO];
__device__ float  g_Sp[3 * 64 * OO];
__device__ float  g_Tp[3 * 64 * OO];

// ---------------------------------------------------------------------------
// Helpers (sm_80-era PTX only — must assemble under compute_103)
// ---------------------------------------------------------------------------
__device__ __forceinline__ uint32_t smem_to_u32(const void* p) {
    uint32_t a;
    asm("{ .reg .u64 t; cvta.to.shared.u64 t, %1; cvt.u32.u64 %0, t; }"
        : "=r"(a) : "l"(p));
    return a;
}
__device__ __forceinline__ void cp16(uint32_t dst, const void* src) {
    asm volatile("cp.async.cg.shared.global [%0], [%1], 16;"
                 :: "r"(dst), "l"(src) : "memory");
}
__device__ __forceinline__ void ldm_x4(uint32_t* r, uint32_t addr) {
    asm volatile("ldmatrix.sync.aligned.m8n8.x4.shared.b16 {%0,%1,%2,%3}, [%4];"
                 : "=r"(r[0]), "=r"(r[1]), "=r"(r[2]), "=r"(r[3]) : "r"(addr));
}
__device__ __forceinline__ void mma_fp16(float* c, const uint32_t* a,
                                         uint32_t b0, uint32_t b1) {
    asm volatile(
        "mma.sync.aligned.m16n8k16.row.col.f32.f16.f16.f32 "
        "{%0,%1,%2,%3}, {%4,%5,%6,%7}, {%8,%9}, {%0,%1,%2,%3};"
        : "+f"(c[0]), "+f"(c[1]), "+f"(c[2]), "+f"(c[3])
        : "r"(a[0]), "r"(a[1]), "r"(a[2]), "r"(a[3]), "r"(b0), "r"(b1));
}

// Block-wide (128 threads) mean/rstd reduction.
__device__ __forceinline__ void row_stats_finish(float s, float ss, int row,
                                                 float* mean, float* rstd, int tid) {
    #pragma unroll
    for (int o = 16; o > 0; o >>= 1) {
        s  += __shfl_xor_sync(0xFFFFFFFFu, s,  o);
        ss += __shfl_xor_sync(0xFFFFFFFFu, ss, o);
    }
    __shared__ float sh_s[4], sh_ss[4];
    const int w = tid >> 5;
    if ((tid & 31) == 0) { sh_s[w] = s; sh_ss[w] = ss; }
    __syncthreads();
    if (tid == 0) {
        s  = sh_s[0] + sh_s[1] + sh_s[2] + sh_s[3];
        ss = sh_ss[0] + sh_ss[1] + sh_ss[2] + sh_ss[3];
        const float mn  = s * (1.0f / DD);
        const float var = ss * (1.0f / DD) - mn * mn;
        mean[row] = mn;
        rstd[row] = rsqrtf(var + 1e-5f);
    }
}

// ---------------------------------------------------------------------------
// Block 1 stats: read fp32 x, write fp16(x) + row mean/rstd (stats from fp32).
// ---------------------------------------------------------------------------
__global__ void stats32_kernel(const float* __restrict__ x,
                               __half* __restrict__ x16,
                               float* __restrict__ mean,
                               float* __restrict__ rstd) {
    const int row = blockIdx.x;
    const int tid = threadIdx.x;
    float4 v = reinterpret_cast<const float4*>(x + (size_t)row * DD)[tid];

    __half2* p = reinterpret_cast<__half2*>(x16 + (size_t)row * DD);
    p[tid * 2]     = __halves2half2(__float2half_rn(v.x), __float2half_rn(v.y));
    p[tid * 2 + 1] = __halves2half2(__float2half_rn(v.z), __float2half_rn(v.w));

    float s  = v.x + v.y + v.z + v.w;
    float ss = v.x * v.x + v.y * v.y + v.z * v.z + v.w * v.w;
    row_stats_finish(s, ss, row, mean, rstd, tid);
}

// ---------------------------------------------------------------------------
// Stats from fp16 input (block 2: b==nullptr). Block 3 (b!=nullptr):
// forms fp16(a+b), writes to sum_out, stats from the rounded sum.
// ---------------------------------------------------------------------------
__global__ void stats16_kernel(const __half* __restrict__ a,
                               const __half* __restrict__ b,
                               __half* __restrict__ sum_out,
                               float* __restrict__ mean,
                               float* __restrict__ rstd) {
    const int row = blockIdx.x;
    const int tid = threadIdx.x;

    const float2 rawa = reinterpret_cast<const float2*>(a + (size_t)row * DD)[tid];
    __half2 a0 = *reinterpret_cast<const __half2*>(&rawa.x);
    __half2 a1 = *reinterpret_cast<const __half2*>(&rawa.y);
    float v0 = __half2float(__low2half(a0)),  v1 = __half2float(__high2half(a0));
    float v2 = __half2float(__low2half(a1)),  v3 = __half2float(__high2half(a1));

    if (b != nullptr) {
        const float2 rawb = reinterpret_cast<const float2*>(b + (size_t)row * DD)[tid];
        __half2 b0 = *reinterpret_cast<const __half2*>(&rawb.x);
        __half2 b1 = *reinterpret_cast<const __half2*>(&rawb.y);
        v0 += __half2float(__low2half(b0));  v1 += __half2float(__high2half(b0));
        v2 += __half2float(__low2half(b1));  v3 += __half2float(__high2half(b1));
        __half h0 = __float2half_rn(v0), h1 = __float2half_rn(v1);
        __half h2 = __float2half_rn(v2), h3 = __float2half_rn(v3);
        __half2* p = reinterpret_cast<__half2*>(sum_out + (size_t)row * DD);
        p[tid * 2]     = __halves2half2(h0, h1);
        p[tid * 2 + 1] = __halves2half2(h2, h3);
        v0 = __half2float(h0); v1 = __half2float(h1);
        v2 = __half2float(h2); v3 = __half2float(h3);
    }

    float s  = v0 + v1 + v2 + v3;
    float ss = v0 * v0 + v1 * v1 + v2 * v2 + v3 * v3;
    row_stats_finish(s, ss, row, mean, rstd, tid);
}

// ---------------------------------------------------------------------------
// Unified weight prep, all 3 layers in one launch. grid (64, 3), 256 threads.
// Block (i, l): k rows [8i, 8i+8) of layer l.
//  - stages W tile in SMEM (coalesced read)
//  - writes wg[l][n][k0..k0+7] = fp16(g[k]*W[k][n])  (16B per row-segment)
//  - writes S/T partials Sp/Tp[l][i][n]
// ---------------------------------------------------------------------------
__global__ __launch_bounds__(256)
void wprep_kernel(const float* __restrict__ W1, const float* __restrict__ W2,
                  const float* __restrict__ W3,
                  const float* __restrict__ g1, const float* __restrict__ g2,
                  const float* __restrict__ g3,
                  const float* __restrict__ b1, const float* __restrict__ b2,
                  const float* __restrict__ b3,
                  __half* __restrict__ wg,
                  float* __restrict__ Sp, float* __restrict__ Tp) {
    const int l = blockIdx.y;
    const float* W = (l == 0) ? W1 : (l == 1) ? W2 : W3;
    const float* g = (l == 0) ? g1 : (l == 1) ? g2 : g3;
    const float* b = (l == 0) ? b1 : (l == 1) ? b2 : b3;
    __half* wgo = wg + (size_t)l * DD * OO;
    float* Spo = Sp + (size_t)l * 64 * OO;
    float* Tpo = Tp + (size_t)l * 64 * OO;

    const int tid = threadIdx.x;
    const int k0 = blockIdx.x * 8;

    __shared__ float sw[8][513];
    for (int idx = tid; idx < 8 * 512; idx += 256) {
        const int kk = idx >> 9;
        const int n  = idx & 511;
        sw[kk][n] = W[(size_t)(k0 + kk) * OO + n];
    }
    __shared__ float sg[8], sb[8];
    if (tid < 8)            sg[tid] = g[k0 + tid];
    else if (tid < 16)      sb[tid - 8] = b[k0 + tid - 8];
    __syncthreads();

    #pragma unroll
    for (int half = 0; half < 2; half++) {
        const int n = tid + half * 256;
        float s = 0.f, t = 0.f;
        __align__(16) __half h[8];
        #pragma unroll
        for (int i = 0; i < 8; i++) {
            const float w = sw[i][n];
            const float gw = sg[i] * w;
            s += gw;
            t += sb[i] * w;
            h[i] = __float2half_rn(gw);
        }
        *reinterpret_cast<uint4*>(wgo + (size_t)n * DD + k0) =
            *reinterpret_cast<const uint4*>(h);
        Spo[blockIdx.x * OO + n] = s;
        Tpo[blockIdx.x * OO + n] = t;
    }
}

// ---------------------------------------------------------------------------
// S/T reduce, all layers: grid (2, 3) x 256 threads.
// ---------------------------------------------------------------------------
__global__ void str_kernel(const float* __restrict__ Sp,
                           const float* __restrict__ Tp,
                           float* __restrict__ S,
                           float* __restrict__ T) {
    const int l = blockIdx.y;
    const int n = blockIdx.x * 256 + threadIdx.x;
    const float* Spo = Sp + (size_t)l * 64 * OO;
    const float* Tpo = Tp + (size_t)l * 64 * OO;
    float s = 0.f, t = 0.f;
    #pragma unroll 8
    for (int i = 0; i < 64; i++) {
        s += Spo[i * OO + n];
        t += Tpo[i * OO + n];
    }
    S[l * OO + n] = s;
    T[l * OO + n] = t;
}

// ---------------------------------------------------------------------------
// fp16 HMMA GEMM with fused LN affine epilogue:
//   out = rstd[row] * (A@Wg^T - mean[row]*S[col]) + T[col]   (+tanh)
// A raw fp16 [M,K]; Wg [N,K] fp16. CTA 128x128, BK=32, 3-stage cp.async.
// ---------------------------------------------------------------------------
template <bool TANH, typename OutT>
__global__ __launch_bounds__(256, 2)
void gemm_ln_kernel(const __half* __restrict__ A,
                    const __half* __restrict__ B,
                    const float* __restrict__ mean,
                    const float* __restrict__ rstd,
                    const float* __restrict__ S,
                    const float* __restrict__ T,
                    OutT* __restrict__ C) {
    extern __shared__ char smem[];
    const uint32_t sb = smem_to_u32(smem);

    const int tid  = threadIdx.x;
    const int lane = tid & 31;
    const int wid  = tid >> 5;
    const int m0 = blockIdx.y * 128;
    const int n0 = blockIdx.x * 128;
    const int warp_m = (wid >> 1) * 32;
    const int warp_n = (wid & 1) * 64;

    float acc[2][8][4];
    #pragma unroll
    for (int i = 0; i < 2; i++)
        #pragma unroll
        for (int j = 0; j < 8; j++)
            #pragma unroll
            for (int q = 0; q < 4; q++) acc[i][j][q] = 0.0f;

    const int arow  = warp_m + (lane & 7) + ((lane >> 3) & 1) * 8;
    const int akblk = (lane >> 4) & 1;
    const int ax    = arow & 3;
    const int brow  = warp_n + (lane & 7) + ((lane >> 4) & 1) * 8;
    const int bkblk = (lane >> 3) & 1;
    const int bx    = brow & 3;

    #define AOFF(mt, kb) \
        (uint32_t)((arow + (mt) * 16) * 64 + (((((kb) >> 3) + akblk) ^ ax) & 3) * 16)
    #define BOFF(jj, kb) \
        (uint32_t)((brow + (jj) * 16) * 64 + (((((kb) >> 3) + bkblk) ^ bx) & 3) * 16)

    const int c0row = tid >> 2,          c0ch = tid & 3;
    const int c1row = (tid + 256) >> 2;
    const uint32_t d0 = (uint32_t)(c0row * 64 + ((c0ch ^ (c0row & 3)) << 4));
    const uint32_t d1 = (uint32_t)(c1row * 64 + ((c0ch ^ (c1row & 3)) << 4));
    const size_t gA0 = (size_t)(m0 + c0row) * DD + c0ch * 8;
    const size_t gA1 = (size_t)(m0 + c1row) * DD + c0ch * 8;
    const size_t gB0 = (size_t)(n0 + c0row) * DD + c0ch * 8;
    const size_t gB1 = (size_t)(n0 + c1row) * DD + c0ch * 8;

    #define LOAD_STAGE(it, st) do {                                      \
        const int _k0 = (it) * 32;                                       \
        const uint32_t _sa = sb + (uint32_t)(st) * 16384u;               \
        const uint32_t _sbb = _sa + 8192u;                               \
        cp16(_sa + d0, A + gA0 + _k0);                                   \
        cp16(_sa + d1, A + gA1 + _k0);                                   \
        cp16(_sbb + d0, B + gB0 + _k0);                                  \
        cp16(_sbb + d1, B + gB1 + _k0);                                  \
        asm volatile("cp.async.commit_group;" ::: "memory");             \
    } while (0)

    LOAD_STAGE(0, 0);
    LOAD_STAGE(1, 1);

    const int NK = DD / 32;   // 16
    int st = 0;
    for (int it = 0; it < NK; it++) {
        if (it + 1 < NK) {
            asm volatile("cp.async.wait_group 1;" ::: "memory");
        } else {
            asm volatile("cp.async.wait_group 0;" ::: "memory");
        }
        __syncthreads();

        if (it + 2 < NK) {
            int st2 = st + 2; if (st2 >= 3) st2 -= 3;
            LOAD_STAGE(it + 2, st2);
        }

        const uint32_t sa = sb + (uint32_t)st * 16384u;
        const uint32_t sbB = sa + 8192u;
        #pragma unroll
        for (int ks = 0; ks < 2; ks++) {
            const int kb = ks * 16;
            uint32_t af[2][4];
            #pragma unroll
            for (int mt = 0; mt < 2; mt++)
                ldm_x4(af[mt], sa + AOFF(mt, kb));
            uint32_t bf[4][4];
            #pragma unroll
            for (int jj = 0; jj < 4; jj++)
                ldm_x4(bf[jj], sbB + BOFF(jj, kb));
            #pragma unroll
            for (int j = 0; j < 8; j++) {
                const int jj = j >> 1, jh = (j & 1) * 2;
                const uint32_t b0 = bf[jj][jh], b1 = bf[jj][jh + 1];
                #pragma unroll
                for (int mt = 0; mt < 2; mt++)
                    mma_fp16(acc[mt][j], af[mt], b0, b1);
            }
        }
        if (++st >= 3) st = 0;
    }
    #undef LOAD_STAGE
    #undef AOFF
    #undef BOFF

    // Epilogue: fused LN affine (+tanh), write OutT
    #pragma unroll
    for (int mt = 0; mt < 2; mt++) {
        const int r0 = m0 + warp_m + mt * 16 + (lane >> 2);
        const int r1 = r0 + 8;
        const float mn0 = mean[r0], rs0 = rstd[r0];
        const float mn1 = mean[r1], rs1 = rstd[r1];
        #pragma unroll
        for (int j = 0; j < 8; j++) {
            const int col = n0 + warp_n + j * 8 + (lane & 3) * 2;
            const float s0 = S[col], s1 = S[col + 1];
            const float t0 = T[col], t1 = T[col + 1];
            float v0 = rs0 * (acc[mt][j][0] - mn0 * s0) + t0;
            float v1 = rs0 * (acc[mt][j][1] - mn0 * s1) + t1;
            float v2 = rs1 * (acc[mt][j][2] - mn1 * s0) + t0;
            float v3 = rs1 * (acc[mt][j][3] - mn1 * s1) + t1;
            if (TANH) { v0 = tanhf(v0); v1 = tanhf(v1); v2 = tanhf(v2); v3 = tanhf(v3); }
            if (sizeof(OutT) == 2) {
                __half2* p0 = reinterpret_cast<__half2*>((__half*)C + (size_t)r0 * OO + col);
                __half2* p1 = reinterpret_cast<__half2*>((__half*)C + (size_t)r1 * OO + col);
                *p0 = __halves2half2(__float2half_rn(v0), __float2half_rn(v1));
                *p1 = __halves2half2(__float2half_rn(v2), __float2half_rn(v3));
            } else {
                *reinterpret_cast<float2*>((float*)C + (size_t)r0 * OO + col) = make_float2(v0, v1);
                *reinterpret_cast<float2*>((float*)C + (size_t)r1 * OO + col) = make_float2(v2, v3);
            }
        }
    }
}

// ---------------------------------------------------------------------------
// SMEM-resident masked softmax over axis=1 (N=256), in-place on out[B,N,O].
// grid (BB, 8), 256 threads; each block owns a 256n x 64o panel staged in
// 64KB dynamic SMEM: one global read + one global write.
// ---------------------------------------------------------------------------
__global__ __launch_bounds__(256)
void softmax_kernel(float* __restrict__ out, const unsigned* __restrict__ mask) {
    extern __shared__ float sv[];   // [256][64]
    __shared__ unsigned smask[NN];
    __shared__ float red_m[4][64], red_s[4][64];

    const int b  = blockIdx.x;
    const int o0 = blockIdx.y * 64;
    const int tid = threadIdx.x;

    smask[tid] = mask[(size_t)b * NN + tid];
    __syncthreads();
    int any = __syncthreads_or(smask[tid] != 0u);
    if (!any && tid == 0) smask[0] = 1u;
    __syncthreads();

    float* base = out + (size_t)b * NN * OO + o0;

    // Stage panel (coalesced: 64 consecutive floats per row)
    for (int idx = tid; idx < NN * 64; idx += 256) {
        const int n = idx >> 6, c = idx & 63;
        sv[idx] = base[(size_t)n * OO + c];
    }
    __syncthreads();

    // Per-column online max/sum, 4 n-segments
    const int col = tid & 63;
    const int seg = tid >> 6;
    float m = -INFINITY, s = 0.0f;
    for (int n = seg * 64; n < seg * 64 + 64; n++) {
        if (smask[n]) {
            const float v = sv[n * 64 + col];
            const float nm = fmaxf(m, v);
            s = s * __expf(m - nm) + __expf(v - nm);
            m = nm;
        }
    }
    red_m[seg][col] = m;
    red_s[seg][col] = s;
    __syncthreads();

    if (seg == 0) {
        float M = red_m[0][col];
        #pragma unroll
        for (int i = 1; i < 4; i++) M = fmaxf(M, red_m[i][col]);
        float SS = 0.0f;
        #pragma unroll
        for (int i = 0; i < 4; i++) {
            const float mi = red_m[i][col];
            if (mi != -INFINITY) SS += red_s[i][col] * __expf(mi - M);
        }
        red_m[0][col] = M;
        red_s[0][col] = 1.0f / SS;
    }
    __syncthreads();

    const float M  = red_m[0][col];
    const float rs = red_s[0][col];
    for (int n = seg * 64; n < seg * 64 + 64; n++) {
        const float v = smask[n] ? __expf(sv[n * 64 + col] - M) * rs : 0.0f;
        sv[n * 64 + col] = v;
    }
    __syncthreads();

    for (int idx = tid; idx < NN * 64; idx += 256) {
        const int n = idx >> 6, c = idx & 63;
        base[(size_t)n * OO + c] = sv[idx];
    }
}

// ---------------------------------------------------------------------------
// Launch
// ---------------------------------------------------------------------------
extern "C" void kernel_launch(void* const* d_in, const int* in_sizes, int n_in,
                              void* d_out, int out_size) {
    const float*    Obs  = (const float*)d_in[0];
    const unsigned* mask = (const unsigned*)d_in[1];
    const float* g1 = (const float*)d_in[2];
    const float* b1 = (const float*)d_in[3];
    const float* W1 = (const float*)d_in[4];
    const float* g2 = (const float*)d_in[5];
    const float* b2 = (const float*)d_in[6];
    const float* W2 = (const float*)d_in[7];
    const float* g3 = (const float*)d_in[8];
    const float* b3 = (const float*)d_in[9];
    const float* W3 = (const float*)d_in[10];
    float* out = (float*)d_out;

    __half *x16, *h1, *h2, *wg;
    float *mean, *rstd, *S, *T, *Sp, *Tp;
    cudaGetSymbolAddress((void**)&x16, g_x16);
    cudaGetSymbolAddress((void**)&h1, g_h1);
    cudaGetSymbolAddress((void**)&h2, g_h2);
    cudaGetSymbolAddress((void**)&wg, g_wg);
    cudaGetSymbolAddress((void**)&mean, g_mean);
    cudaGetSymbolAddress((void**)&rstd, g_rstd);
    cudaGetSymbolAddress((void**)&S, g_S);
    cudaGetSymbolAddress((void**)&T, g_T);
    cudaGetSymbolAddress((void**)&Sp, g_Sp);
    cudaGetSymbolAddress((void**)&Tp, g_Tp);

    static bool attr_done = false;
    const int DSMEM = 49152;          // GEMM: 3 stages x 16KB
    const int SMEM_SOFT = NN * 64 * 4;  // 64KB
    if (!attr_done) {
        cudaFuncSetAttribute(gemm_ln_kernel<true, __half>,
                             cudaFuncAttributeMaxDynamicSharedMemorySize, DSMEM);
        cudaFuncSetAttribute(gemm_ln_kernel<false, float>,
                             cudaFuncAttributeMaxDynamicSharedMemorySize, DSMEM);
        cudaFuncSetAttribute(softmax_kernel,
                             cudaFuncAttributeMaxDynamicSharedMemorySize, SMEM_SOFT);
        attr_done = true;
    }

    const dim3 gGemm(OO / 128, MROWS / 128);

    // All weight prep up-front (depends only on inputs)
    wprep_kernel<<<dim3(64, 3), 256>>>(W1, W2, W3, g1, g2, g3, b1, b2, b3,
                                       wg, Sp, Tp);
    str_kernel<<<dim3(2, 3), 256>>>(Sp, Tp, S, T);

    // Block 1
    stats32_kernel<<<MROWS, 128>>>(Obs, x16, mean, rstd);
    gemm_ln_kernel<true, __half><<<gGemm, 256, DSMEM>>>(
        x16, wg, mean, rstd, S, T, h1);

    // Block 2
    stats16_kernel<<<MROWS, 128>>>(h1, nullptr, nullptr, mean, rstd);
    gemm_ln_kernel<true, __half><<<gGemm, 256, DSMEM>>>(
        h1, wg + (size_t)DD * OO, mean, rstd, S + OO, T + OO, h2);

    // Block 3 (residual h1+h2, no activation, fp32 out)
    stats16_kernel<<<MROWS, 128>>>(h1, h2, x16, mean, rstd);
    gemm_ln_kernel<false, float><<<gGemm, 256, DSMEM>>>(
        x16, wg + 2 * (size_t)DD * OO, mean, rstd, S + 2 * OO, T + 2 * OO, out);

    // Masked softmax over axis=1, in place
    softmax_kernel<<<dim3(BB, 8), 256, SMEM_SOFT>>>(out, mask);
}